// round 3
// baseline (speedup 1.0000x reference)
#include <cuda_runtime.h>
#include <math.h>

#define LEAKY_SLOPE 0.01f
#define EPS_C 0.1f
#define GAMMA_C 0.1f

#define NN 50000
#define EE 600000

// ---------------- scratch ----------------
__device__ __align__(16) float g_h   [NN * 128];
__device__ __align__(16) float g_h2  [NN * 64];
__device__ __align__(16) float g_msg [NN * 128];
__device__ __align__(16) float g_anti[NN * 128];
__device__ __align__(16) float g_agg [NN * 128];
__device__ int   g_deg [NN];
__device__ float g_dinv[NN];
__device__ int   g_src [EE];
__device__ int   g_dst [EE];
__device__ int   g_is64;

__device__ __forceinline__ float lky(float x) { return x > 0.f ? x : LEAKY_SLOPE * x; }
__device__ __forceinline__ int clampN(int v) { return v < 0 ? 0 : (v >= NN ? NN - 1 : v); }

// ---------------- edge dtype probe + convert (block layout: [2, E] row-major) ----------------
__global__ void probe_kernel(const unsigned int* __restrict__ w) {
    __shared__ int fl;
    if (threadIdx.x == 0) fl = 0;
    __syncthreads();
    for (int i = 1 + 2 * (int)threadIdx.x; i < 16384; i += 2 * (int)blockDim.x)
        if (w[i] != 0u) fl = 1;
    __syncthreads();
    if (threadIdx.x == 0) g_is64 = (fl == 0) ? 1 : 0;
}

__global__ void convert_edges(const void* __restrict__ raw) {
    int i = blockIdx.x * blockDim.x + threadIdx.x;
    if (i >= EE) return;
    int s, d;
    if (g_is64) {
        const long long* p = (const long long*)raw;
        s = (int)p[i];
        d = (int)p[EE + i];
    } else {
        const int* p = (const int*)raw;
        s = p[i];
        d = p[EE + i];
    }
    g_src[i] = clampN(s);
    g_dst[i] = clampN(d);
}

// ---------------- degree / norm ----------------
__global__ void zero_deg() {
    int i = blockIdx.x * blockDim.x + threadIdx.x;
    if (i < NN) g_deg[i] = 0;
}
__global__ void hist_kernel() {
    int i = blockIdx.x * blockDim.x + threadIdx.x;
    if (i < EE) atomicAdd(&g_deg[g_dst[i]], 1);
}
__global__ void dinv_kernel() {
    int i = blockIdx.x * blockDim.x + threadIdx.x;
    if (i < NN) g_dinv[i] = rsqrtf((float)(g_deg[i] + 1));  // +1 self loop
}

// ---------------- linear: C[i][j] = leaky( sum_k act(A[i][k]) * Wt[j][k] + b[j] ) ----------------
__global__ void k_linear(const float* __restrict__ A, const float* __restrict__ Wt,
                         const float* __restrict__ b, float* __restrict__ C,
                         int K, int J, int preL) {
    int node = (blockIdx.x * blockDim.x + threadIdx.x) >> 5;
    if (node >= NN) return;
    int lane = threadIdx.x & 31;
    const float* ar = A + (size_t)node * K;
    for (int c = 0; c < J; c += 32) {
        int j = c + lane;
        float acc = b[j];
        for (int k = 0; k < K; k++) {
            float av = ar[k];
            if (preL) av = lky(av);
            acc += av * Wt[(size_t)j * K + k];
        }
        C[(size_t)node * J + j] = lky(acc);
    }
}

// ---------------- msg[i][j] = sum_k h[i][k] * Wg[k][j] ----------------
__global__ void k_msg(const float* __restrict__ h, const float* __restrict__ Wg,
                      float* __restrict__ msg, int H) {
    int node = (blockIdx.x * blockDim.x + threadIdx.x) >> 5;
    if (node >= NN) return;
    int lane = threadIdx.x & 31;
    const float* hr = h + (size_t)node * H;
    for (int c = 0; c < H; c += 32) {
        int j = c + lane;
        float acc = 0.f;
        for (int k = 0; k < H; k++)
            acc += hr[k] * Wg[(size_t)k * H + j];
        msg[(size_t)node * H + j] = acc;
    }
}

// ---------------- anti[i][j] = sum_k h[i][k]*(W[j][k]-W[k][j]) - gamma*h[i][j] ----------------
__global__ void k_anti(const float* __restrict__ h, const float* __restrict__ W,
                       float* __restrict__ anti, int H) {
    int node = (blockIdx.x * blockDim.x + threadIdx.x) >> 5;
    if (node >= NN) return;
    int lane = threadIdx.x & 31;
    const float* hr = h + (size_t)node * H;
    for (int c = 0; c < H; c += 32) {
        int j = c + lane;
        float acc = 0.f;
        for (int k = 0; k < H; k++)
            acc += hr[k] * (W[(size_t)j * H + k] - W[(size_t)k * H + j]);
        anti[(size_t)node * H + j] = acc - GAMMA_C * hr[j];
    }
}

// ---------------- zero + edge-parallel scatter ----------------
__global__ void k_zero(float* __restrict__ p, int n) {
    int i = blockIdx.x * blockDim.x + threadIdx.x;
    if (i < n) p[i] = 0.f;
}
__global__ void k_scatter(const float* __restrict__ msg, float* __restrict__ agg, int H) {
    int e = (blockIdx.x * blockDim.x + threadIdx.x) >> 5;
    if (e >= EE) return;
    int lane = threadIdx.x & 31;
    int s = g_src[e], d = g_dst[e];
    float w = g_dinv[s] * g_dinv[d];
    const float* m = msg + (size_t)s * H;
    float* a = agg + (size_t)d * H;
    for (int j = lane; j < H; j += 32)
        atomicAdd(&a[j], m[j] * w);
}

// ---------------- h += eps * tanh(anti + agg + self + bias) ----------------
__global__ void k_update(float* __restrict__ h, const float* __restrict__ anti,
                         const float* __restrict__ agg, const float* __restrict__ msg,
                         const float* __restrict__ bias, int H) {
    long long idx = (long long)blockIdx.x * blockDim.x + threadIdx.x;
    if (idx >= (long long)NN * H) return;
    int i = (int)(idx / H);
    int j = (int)(idx % H);
    float di = g_dinv[i];
    float self = msg[idx] * di * di;
    h[idx] += EPS_C * tanhf(anti[idx] + agg[idx] + self + bias[j]);
}

// ---------------- fc + log_softmax, thread per node ----------------
__global__ void k_fc(const float* __restrict__ h2, const float* __restrict__ wfc,
                     const float* __restrict__ bfc, float* __restrict__ out) {
    int i = blockIdx.x * blockDim.x + threadIdx.x;
    if (i >= NN) return;
    float hv[64];
    const float* hr = h2 + (size_t)i * 64;
    for (int k = 0; k < 64; k++) hv[k] = hr[k];
    float lg[40];
    float m = -1e30f;
    for (int j = 0; j < 40; j++) {
        float acc = bfc[j];
        for (int k = 0; k < 64; k++)
            acc += hv[k] * wfc[(size_t)j * 64 + k];
        lg[j] = acc;
        m = fmaxf(m, acc);
    }
    float s = 0.f;
    for (int j = 0; j < 40; j++) s += expf(lg[j] - m);
    float lse = m + logf(s);
    float* o = out + (size_t)i * 40;
    for (int j = 0; j < 40; j++) o[j] = lg[j] - lse;
}

// ---------------- launch ----------------
extern "C" void kernel_launch(void* const* d_in, const int* in_sizes, int n_in,
                              void* d_out, int out_size) {
    const float* x      = (const float*)d_in[0];
    const void*  edges  = d_in[1];
    const float* w_hid  = (const float*)d_in[2];
    const float* b_hid  = (const float*)d_in[3];
    const float* W_a1   = (const float*)d_in[4];
    const float* gcn_w1 = (const float*)d_in[5];
    const float* b_a1   = (const float*)d_in[6];
    const float* w_hid2 = (const float*)d_in[7];
    const float* b_hid2 = (const float*)d_in[8];
    const float* W_a2   = (const float*)d_in[9];
    const float* gcn_w2 = (const float*)d_in[10];
    const float* b_a2   = (const float*)d_in[11];
    const float* w_fc   = (const float*)d_in[12];
    const float* b_fc   = (const float*)d_in[13];
    float* out = (float*)d_out;

    probe_kernel<<<1, 1024>>>((const unsigned int*)edges);
    convert_edges<<<(EE + 255) / 256, 256>>>(edges);
    zero_deg<<<(NN + 255) / 256, 256>>>();
    hist_kernel<<<(EE + 255) / 256, 256>>>();
    dinv_kernel<<<(NN + 255) / 256, 256>>>();

    int nodeWarps = (NN * 32 + 255) / 256;
    int edgeWarps = (EE * 32 + 255) / 256;

    // layer0: h = leaky(x @ w_hid.T + b_hid)
    k_linear<<<nodeWarps, 256>>>(x, w_hid, b_hid, g_h, 256, 128, 0);

    // conv1: 3 iterations, H=128
    for (int it = 0; it < 3; it++) {
        k_msg<<<nodeWarps, 256>>>(g_h, gcn_w1, g_msg, 128);
        k_anti<<<nodeWarps, 256>>>(g_h, W_a1, g_anti, 128);
        k_zero<<<(NN * 128 + 255) / 256, 256>>>(g_agg, NN * 128);
        k_scatter<<<edgeWarps, 256>>>(g_msg, g_agg, 128);
        k_update<<<(NN * 128 + 255) / 256, 256>>>(g_h, g_anti, g_agg, g_msg, b_a1, 128);
    }

    // hid2: h2 = leaky(leaky(h) @ w_hid2.T + b_hid2)
    k_linear<<<nodeWarps, 256>>>(g_h, w_hid2, b_hid2, g_h2, 128, 64, 1);

    // conv2: 1 iteration, H=64
    k_msg<<<nodeWarps, 256>>>(g_h2, gcn_w2, g_msg, 64);
    k_anti<<<nodeWarps, 256>>>(g_h2, W_a2, g_anti, 64);
    k_zero<<<(NN * 64 + 255) / 256, 256>>>(g_agg, NN * 64);
    k_scatter<<<edgeWarps, 256>>>(g_msg, g_agg, 64);
    k_update<<<(NN * 64 + 255) / 256, 256>>>(g_h2, g_anti, g_agg, g_msg, b_a2, 64);

    // fc + log_softmax
    k_fc<<<(NN + 255) / 256, 256>>>(g_h2, w_fc, b_fc, out);
}

// round 6
// speedup vs baseline: 1.5625x; 1.5625x over previous
#include <cuda_runtime.h>
#include <math.h>

#define LEAKY_SLOPE 0.01f
#define EPS_C 0.1f
#define GAMMA_C 0.1f

#define NN 50000
#define EE 600000

// ---------------- scratch (node data only; no weight copies!) ----------------
__device__ __align__(16) float g_h   [NN * 128];
__device__ __align__(16) float g_h2  [NN * 64];
__device__ __align__(16) float g_msg [NN * 128];
__device__ __align__(16) float g_anti[NN * 128];
__device__ __align__(16) float g_agg [NN * 128];
__device__ int   g_deg [NN];
__device__ float g_dinv[NN];
__device__ int   g_src [EE];
__device__ int   g_dst [EE];
__device__ int   g_is64;

__device__ __forceinline__ float lky(float x) { return x > 0.f ? x : LEAKY_SLOPE * x; }
__device__ __forceinline__ int clampN(int v) { return v < 0 ? 0 : (v >= NN ? NN - 1 : v); }

// ---------------- edge dtype probe + convert (layout [2, E] row-major) ----------------
__global__ void probe_kernel(const unsigned int* __restrict__ w) {
    __shared__ int fl;
    if (threadIdx.x == 0) fl = 0;
    __syncthreads();
    for (int i = 1 + 2 * (int)threadIdx.x; i < 16384; i += 2 * (int)blockDim.x)
        if (w[i] != 0u) fl = 1;
    __syncthreads();
    if (threadIdx.x == 0) g_is64 = (fl == 0) ? 1 : 0;
}

__global__ void convert_edges(const void* __restrict__ raw) {
    int i = blockIdx.x * blockDim.x + threadIdx.x;
    if (i >= EE) return;
    int s, d;
    if (g_is64) {
        const long long* p = (const long long*)raw;
        s = (int)p[i];
        d = (int)p[EE + i];
    } else {
        const int* p = (const int*)raw;
        s = p[i];
        d = p[EE + i];
    }
    g_src[i] = clampN(s);
    g_dst[i] = clampN(d);
}

// ---------------- degree / norm ----------------
__global__ void zero_deg() {
    int i = blockIdx.x * blockDim.x + threadIdx.x;
    if (i < NN) g_deg[i] = 0;
}
__global__ void hist_kernel() {
    int i = blockIdx.x * blockDim.x + threadIdx.x;
    if (i < EE) atomicAdd(&g_deg[g_dst[i]], 1);
}
__global__ void dinv_kernel() {
    int i = blockIdx.x * blockDim.x + threadIdx.x;
    if (i < NN) g_dinv[i] = rsqrtf((float)(g_deg[i] + 1));  // +1 self loop
}

// ---------------- linear (lane = k, coalesced weight rows, butterfly reduce) ----------------
// C[i][j] = lky( b[j] + sum_k act(A[i][k]) * Wt[j*K+k] ),  Wt raw [J][K] layout.
template<int K, int J, int PREL>
__global__ void __launch_bounds__(256) k_linear(const float* __restrict__ A,
                                                const float* __restrict__ Wt,
                                                const float* __restrict__ b,
                                                float* __restrict__ C) {
    int node = (blockIdx.x * blockDim.x + threadIdx.x) >> 5;
    if (node >= NN) return;
    int lane = threadIdx.x & 31;
    const float* ar = A + (size_t)node * K;
    float xr[K / 32];
#pragma unroll
    for (int m = 0; m < K / 32; m++) {
        float v = ar[32 * m + lane];
        xr[m] = PREL ? lky(v) : v;
    }
    float outv[J / 32];
#pragma unroll
    for (int c = 0; c < J / 32; c++) outv[c] = 0.f;
    for (int j = 0; j < J; j++) {
        const float* wr = Wt + (size_t)j * K;
        float p = 0.f;
#pragma unroll
        for (int m = 0; m < K / 32; m++)
            p = fmaf(xr[m], wr[32 * m + lane], p);
#pragma unroll
        for (int o = 16; o; o >>= 1) p += __shfl_xor_sync(0xffffffffu, p, o);
        if ((j & 31) == lane) outv[j >> 5] = p;
    }
#pragma unroll
    for (int c = 0; c < J / 32; c++) {
        int j = c * 32 + lane;
        C[(size_t)node * J + j] = lky(outv[c] + b[j]);
    }
}

// ---------------- msg[i][j] = sum_k h[i][k] * Wg[k*H+j]  (verbatim R3 semantics) ----------------
__global__ void k_msg(const float* __restrict__ h, const float* __restrict__ Wg,
                      float* __restrict__ msg, int H) {
    int node = (blockIdx.x * blockDim.x + threadIdx.x) >> 5;
    if (node >= NN) return;
    int lane = threadIdx.x & 31;
    const float* hr = h + (size_t)node * H;
    for (int c = 0; c < H; c += 32) {
        int j = c + lane;
        float acc = 0.f;
        for (int k = 0; k < H; k++)
            acc += hr[k] * Wg[(size_t)k * H + j];
        msg[(size_t)node * H + j] = acc;
    }
}

// ---------------- anti[i][j] = sum_k h[k]*(W[j][k]-W[k][j]) - gamma*h[j] ----------------
// phase A: term1_j = dot(h, W_row_j) via lane=k coalesced loads + butterfly.
// phase B: term2_j via lane=j coalesced column reads (like k_msg).
template<int H>
__global__ void __launch_bounds__(256) k_anti(const float* __restrict__ h,
                                              const float* __restrict__ W,
                                              float* __restrict__ anti) {
    __shared__ float t1[8][H];
    __shared__ float hs[8][H];
    int warp = threadIdx.x >> 5;
    int node = (blockIdx.x * blockDim.x + threadIdx.x) >> 5;
    if (node >= NN) return;
    int lane = threadIdx.x & 31;
    const float* hr = h + (size_t)node * H;
    float xr[H / 32];
#pragma unroll
    for (int m = 0; m < H / 32; m++) {
        xr[m] = hr[32 * m + lane];
        hs[warp][32 * m + lane] = xr[m];
    }
    __syncwarp();
    // phase A
    for (int j = 0; j < H; j++) {
        const float* wr = W + (size_t)j * H;
        float p = 0.f;
#pragma unroll
        for (int m = 0; m < H / 32; m++)
            p = fmaf(xr[m], wr[32 * m + lane], p);
#pragma unroll
        for (int o = 16; o; o >>= 1) p += __shfl_xor_sync(0xffffffffu, p, o);
        if (lane == 0) t1[warp][j] = p;
    }
    __syncwarp();
    // phase B
#pragma unroll
    for (int c = 0; c < H / 32; c++) {
        int j = c * 32 + lane;
        float acc = 0.f;
        for (int k = 0; k < H; k++)
            acc = fmaf(hs[warp][k], W[(size_t)k * H + j], acc);
        anti[(size_t)node * H + j] = t1[warp][j] - acc - GAMMA_C * xr[c];
    }
}

// ---------------- zero + edge-parallel scatter (verbatim R3) ----------------
__global__ void k_zero(float* __restrict__ p, int n) {
    int i = blockIdx.x * blockDim.x + threadIdx.x;
    if (i < n) p[i] = 0.f;
}
__global__ void k_scatter(const float* __restrict__ msg, float* __restrict__ agg, int H) {
    int e = (blockIdx.x * blockDim.x + threadIdx.x) >> 5;
    if (e >= EE) return;
    int lane = threadIdx.x & 31;
    int s = g_src[e], d = g_dst[e];
    float w = g_dinv[s] * g_dinv[d];
    const float* m = msg + (size_t)s * H;
    float* a = agg + (size_t)d * H;
    for (int j = lane; j < H; j += 32)
        atomicAdd(&a[j], m[j] * w);
}

// ---------------- h += eps * tanh(anti + agg + self + bias) (verbatim R3) ----------------
__global__ void k_update(float* __restrict__ h, const float* __restrict__ anti,
                         const float* __restrict__ agg, const float* __restrict__ msg,
                         const float* __restrict__ bias, int H) {
    long long idx = (long long)blockIdx.x * blockDim.x + threadIdx.x;
    if (idx >= (long long)NN * H) return;
    int i = (int)(idx / H);
    int j = (int)(idx % H);
    float di = g_dinv[i];
    float self = msg[idx] * di * di;
    h[idx] += EPS_C * tanhf(anti[idx] + agg[idx] + self + bias[j]);
}

// ---------------- fc + log_softmax, thread per node (verbatim R3) ----------------
__global__ void k_fc(const float* __restrict__ h2, const float* __restrict__ wfc,
                     const float* __restrict__ bfc, float* __restrict__ out) {
    int i = blockIdx.x * blockDim.x + threadIdx.x;
    if (i >= NN) return;
    float hv[64];
    const float* hr = h2 + (size_t)i * 64;
    for (int k = 0; k < 64; k++) hv[k] = hr[k];
    float lg[40];
    float m = -1e30f;
    for (int j = 0; j < 40; j++) {
        float acc = bfc[j];
        for (int k = 0; k < 64; k++)
            acc += hv[k] * wfc[(size_t)j * 64 + k];
        lg[j] = acc;
        m = fmaxf(m, acc);
    }
    float s = 0.f;
    for (int j = 0; j < 40; j++) s += expf(lg[j] - m);
    float lse = m + logf(s);
    float* o = out + (size_t)i * 40;
    for (int j = 0; j < 40; j++) o[j] = lg[j] - lse;
}

// ---------------- launch (same structure as passing R3) ----------------
extern "C" void kernel_launch(void* const* d_in, const int* in_sizes, int n_in,
                              void* d_out, int out_size) {
    const float* x      = (const float*)d_in[0];
    const void*  edges  = d_in[1];
    const float* w_hid  = (const float*)d_in[2];
    const float* b_hid  = (const float*)d_in[3];
    const float* W_a1   = (const float*)d_in[4];
    const float* gcn_w1 = (const float*)d_in[5];
    const float* b_a1   = (const float*)d_in[6];
    const float* w_hid2 = (const float*)d_in[7];
    const float* b_hid2 = (const float*)d_in[8];
    const float* W_a2   = (const float*)d_in[9];
    const float* gcn_w2 = (const float*)d_in[10];
    const float* b_a2   = (const float*)d_in[11];
    const float* w_fc   = (const float*)d_in[12];
    const float* b_fc   = (const float*)d_in[13];
    float* out = (float*)d_out;

    probe_kernel<<<1, 1024>>>((const unsigned int*)edges);
    convert_edges<<<(EE + 255) / 256, 256>>>(edges);
    zero_deg<<<(NN + 255) / 256, 256>>>();
    hist_kernel<<<(EE + 255) / 256, 256>>>();
    dinv_kernel<<<(NN + 255) / 256, 256>>>();

    int nodeWarps = (NN * 32 + 255) / 256;
    int edgeWarps = (EE * 32 + 255) / 256;

    // layer0: h = leaky(x @ w_hid.T + b_hid)
    k_linear<256, 128, 0><<<nodeWarps, 256>>>(x, w_hid, b_hid, g_h);

    // conv1: 3 iterations, H=128
    for (int it = 0; it < 3; it++) {
        k_msg<<<nodeWarps, 256>>>(g_h, gcn_w1, g_msg, 128);
        k_anti<128><<<nodeWarps, 256>>>(g_h, W_a1, g_anti);
        k_zero<<<(NN * 128 + 255) / 256, 256>>>(g_agg, NN * 128);
        k_scatter<<<edgeWarps, 256>>>(g_msg, g_agg, 128);
        k_update<<<(NN * 128 + 255) / 256, 256>>>(g_h, g_anti, g_agg, g_msg, b_a1, 128);
    }

    // hid2: h2 = leaky(leaky(h) @ w_hid2.T + b_hid2)
    k_linear<128, 64, 1><<<nodeWarps, 256>>>(g_h, w_hid2, b_hid2, g_h2);

    // conv2: 1 iteration, H=64
    k_msg<<<nodeWarps, 256>>>(g_h2, gcn_w2, g_msg, 64);
    k_anti<64><<<nodeWarps, 256>>>(g_h2, W_a2, g_anti);
    k_zero<<<(NN * 64 + 255) / 256, 256>>>(g_agg, NN * 64);
    k_scatter<<<edgeWarps, 256>>>(g_msg, g_agg, 64);
    k_update<<<(NN * 64 + 255) / 256, 256>>>(g_h2, g_anti, g_agg, g_msg, b_a2, 64);

    // fc + log_softmax
    k_fc<<<(NN + 255) / 256, 256>>>(g_h2, w_fc, b_fc, out);
}

// round 7
// speedup vs baseline: 2.0383x; 1.3045x over previous
#include <cuda_runtime.h>
#include <math.h>

#define LEAKY_SLOPE 0.01f
#define EPS_C 0.1f
#define GAMMA_C 0.1f

#define NN 50000
#define EE 600000

// ---------------- scratch (node data only; no weight copies!) ----------------
__device__ __align__(16) float g_h   [NN * 128];
__device__ __align__(16) float g_h2  [NN * 64];
__device__ __align__(16) float g_msg [NN * 128];
__device__ __align__(16) float g_anti[NN * 128];
__device__ __align__(16) float g_agg [NN * 128];
__device__ int   g_deg [NN];
__device__ float g_dinv[NN];
__device__ int   g_src [EE];
__device__ int   g_dst [EE];
__device__ int   g_is64;

__device__ __forceinline__ float lky(float x) { return x > 0.f ? x : LEAKY_SLOPE * x; }
__device__ __forceinline__ int clampN(int v) { return v < 0 ? 0 : (v >= NN ? NN - 1 : v); }

// ---------------- edge dtype probe + convert (layout [2, E] row-major) ----------------
__global__ void probe_kernel(const unsigned int* __restrict__ w) {
    __shared__ int fl;
    if (threadIdx.x == 0) fl = 0;
    __syncthreads();
    for (int i = 1 + 2 * (int)threadIdx.x; i < 16384; i += 2 * (int)blockDim.x)
        if (w[i] != 0u) fl = 1;
    __syncthreads();
    if (threadIdx.x == 0) g_is64 = (fl == 0) ? 1 : 0;
}

__global__ void convert_edges(const void* __restrict__ raw) {
    int i = blockIdx.x * blockDim.x + threadIdx.x;
    if (i >= EE) return;
    int s, d;
    if (g_is64) {
        const long long* p = (const long long*)raw;
        s = (int)p[i];
        d = (int)p[EE + i];
    } else {
        const int* p = (const int*)raw;
        s = p[i];
        d = p[EE + i];
    }
    g_src[i] = clampN(s);
    g_dst[i] = clampN(d);
}

// ---------------- degree / norm ----------------
__global__ void zero_deg() {
    int i = blockIdx.x * blockDim.x + threadIdx.x;
    if (i < NN) g_deg[i] = 0;
}
__global__ void hist_kernel() {
    int i = blockIdx.x * blockDim.x + threadIdx.x;
    if (i < EE) atomicAdd(&g_deg[g_dst[i]], 1);
}
__global__ void dinv_kernel() {
    int i = blockIdx.x * blockDim.x + threadIdx.x;
    if (i < NN) g_dinv[i] = rsqrtf((float)(g_deg[i] + 1));  // +1 self loop
}

// ---------------- linear (lane = k, coalesced weight rows, butterfly reduce) ----------------
// C[i][j] = lky( b[j] + sum_k act(A[i][k]) * Wt[j*K+k] ),  Wt raw [J][K] layout. (verbatim R6)
template<int K, int J, int PREL>
__global__ void __launch_bounds__(256) k_linear(const float* __restrict__ A,
                                                const float* __restrict__ Wt,
                                                const float* __restrict__ b,
                                                float* __restrict__ C) {
    int node = (blockIdx.x * blockDim.x + threadIdx.x) >> 5;
    if (node >= NN) return;
    int lane = threadIdx.x & 31;
    const float* ar = A + (size_t)node * K;
    float xr[K / 32];
#pragma unroll
    for (int m = 0; m < K / 32; m++) {
        float v = ar[32 * m + lane];
        xr[m] = PREL ? lky(v) : v;
    }
    float outv[J / 32];
#pragma unroll
    for (int c = 0; c < J / 32; c++) outv[c] = 0.f;
    for (int j = 0; j < J; j++) {
        const float* wr = Wt + (size_t)j * K;
        float p = 0.f;
#pragma unroll
        for (int m = 0; m < K / 32; m++)
            p = fmaf(xr[m], wr[32 * m + lane], p);
#pragma unroll
        for (int o = 16; o; o >>= 1) p += __shfl_xor_sync(0xffffffffu, p, o);
        if ((j & 31) == lane) outv[j >> 5] = p;
    }
#pragma unroll
    for (int c = 0; c < J / 32; c++) {
        int j = c * 32 + lane;
        C[(size_t)node * J + j] = lky(outv[c] + b[j]);
    }
}

// ---------------- msg[i][j] = sum_k h[i][k] * Wg[k*H+j]  (verbatim R6) ----------------
__global__ void k_msg(const float* __restrict__ h, const float* __restrict__ Wg,
                      float* __restrict__ msg, int H) {
    int node = (blockIdx.x * blockDim.x + threadIdx.x) >> 5;
    if (node >= NN) return;
    int lane = threadIdx.x & 31;
    const float* hr = h + (size_t)node * H;
    for (int c = 0; c < H; c += 32) {
        int j = c + lane;
        float acc = 0.f;
        for (int k = 0; k < H; k++)
            acc += hr[k] * Wg[(size_t)k * H + j];
        msg[(size_t)node * H + j] = acc;
    }
}

// ---------------- anti (verbatim R6) ----------------
template<int H>
__global__ void __launch_bounds__(256) k_anti(const float* __restrict__ h,
                                              const float* __restrict__ W,
                                              float* __restrict__ anti) {
    __shared__ float t1[8][H];
    __shared__ float hs[8][H];
    int warp = threadIdx.x >> 5;
    int node = (blockIdx.x * blockDim.x + threadIdx.x) >> 5;
    if (node >= NN) return;
    int lane = threadIdx.x & 31;
    const float* hr = h + (size_t)node * H;
    float xr[H / 32];
#pragma unroll
    for (int m = 0; m < H / 32; m++) {
        xr[m] = hr[32 * m + lane];
        hs[warp][32 * m + lane] = xr[m];
    }
    __syncwarp();
    for (int j = 0; j < H; j++) {
        const float* wr = W + (size_t)j * H;
        float p = 0.f;
#pragma unroll
        for (int m = 0; m < H / 32; m++)
            p = fmaf(xr[m], wr[32 * m + lane], p);
#pragma unroll
        for (int o = 16; o; o >>= 1) p += __shfl_xor_sync(0xffffffffu, p, o);
        if (lane == 0) t1[warp][j] = p;
    }
    __syncwarp();
#pragma unroll
    for (int c = 0; c < H / 32; c++) {
        int j = c * 32 + lane;
        float acc = 0.f;
        for (int k = 0; k < H; k++)
            acc = fmaf(hs[warp][k], W[(size_t)k * H + j], acc);
        anti[(size_t)node * H + j] = t1[warp][j] - acc - GAMMA_C * xr[c];
    }
}

// ---------------- agg init: agg = msg * dinv[i]^2  (folds self-loop term) ----------------
__global__ void k_selfinit(float* __restrict__ agg, const float* __restrict__ msg, int H) {
    long long idx = (long long)blockIdx.x * blockDim.x + threadIdx.x;
    if (idx >= (long long)NN * H) return;
    int i = (int)(idx / H);
    float di = g_dinv[i];
    agg[idx] = msg[idx] * di * di;
}

// ---------------- vector-atomic scatter: H=128 -> red.v4 per lane ----------------
__global__ void k_scatter_v4(const float* __restrict__ msg, float* __restrict__ agg) {
    int e = (blockIdx.x * blockDim.x + threadIdx.x) >> 5;
    if (e >= EE) return;
    int lane = threadIdx.x & 31;
    int s = g_src[e], d = g_dst[e];
    float w = g_dinv[s] * g_dinv[d];
    const float* m = msg + (size_t)s * 128 + lane * 4;
    float v0 = m[0] * w, v1 = m[1] * w, v2 = m[2] * w, v3 = m[3] * w;
    float* a = agg + (size_t)d * 128 + lane * 4;
    asm volatile("red.global.add.v4.f32 [%0], {%1,%2,%3,%4};"
                 :: "l"(a), "f"(v0), "f"(v1), "f"(v2), "f"(v3) : "memory");
}

// ---------------- vector-atomic scatter: H=64 -> red.v2 per lane ----------------
__global__ void k_scatter_v2(const float* __restrict__ msg, float* __restrict__ agg) {
    int e = (blockIdx.x * blockDim.x + threadIdx.x) >> 5;
    if (e >= EE) return;
    int lane = threadIdx.x & 31;
    int s = g_src[e], d = g_dst[e];
    float w = g_dinv[s] * g_dinv[d];
    const float* m = msg + (size_t)s * 64 + lane * 2;
    float v0 = m[0] * w, v1 = m[1] * w;
    float* a = agg + (size_t)d * 64 + lane * 2;
    asm volatile("red.global.add.v2.f32 [%0], {%1,%2};"
                 :: "l"(a), "f"(v0), "f"(v1) : "memory");
}

// ---------------- h += eps * tanh(anti + agg + bias)  (self already in agg) ----------------
__global__ void k_update(float* __restrict__ h, const float* __restrict__ anti,
                         const float* __restrict__ agg, const float* __restrict__ bias,
                         int H) {
    long long idx = (long long)blockIdx.x * blockDim.x + threadIdx.x;
    if (idx >= (long long)NN * H) return;
    int j = (int)(idx % H);
    h[idx] += EPS_C * tanhf(anti[idx] + agg[idx] + bias[j]);
}

// ---------------- fc + log_softmax, thread per node (verbatim R6) ----------------
__global__ void k_fc(const float* __restrict__ h2, const float* __restrict__ wfc,
                     const float* __restrict__ bfc, float* __restrict__ out) {
    int i = blockIdx.x * blockDim.x + threadIdx.x;
    if (i >= NN) return;
    float hv[64];
    const float* hr = h2 + (size_t)i * 64;
    for (int k = 0; k < 64; k++) hv[k] = hr[k];
    float lg[40];
    float m = -1e30f;
    for (int j = 0; j < 40; j++) {
        float acc = bfc[j];
        for (int k = 0; k < 64; k++)
            acc += hv[k] * wfc[(size_t)j * 64 + k];
        lg[j] = acc;
        m = fmaxf(m, acc);
    }
    float s = 0.f;
    for (int j = 0; j < 40; j++) s += expf(lg[j] - m);
    float lse = m + logf(s);
    float* o = out + (size_t)i * 40;
    for (int j = 0; j < 40; j++) o[j] = lg[j] - lse;
}

// ---------------- launch ----------------
extern "C" void kernel_launch(void* const* d_in, const int* in_sizes, int n_in,
                              void* d_out, int out_size) {
    const float* x      = (const float*)d_in[0];
    const void*  edges  = d_in[1];
    const float* w_hid  = (const float*)d_in[2];
    const float* b_hid  = (const float*)d_in[3];
    const float* W_a1   = (const float*)d_in[4];
    const float* gcn_w1 = (const float*)d_in[5];
    const float* b_a1   = (const float*)d_in[6];
    const float* w_hid2 = (const float*)d_in[7];
    const float* b_hid2 = (const float*)d_in[8];
    const float* W_a2   = (const float*)d_in[9];
    const float* gcn_w2 = (const float*)d_in[10];
    const float* b_a2   = (const float*)d_in[11];
    const float* w_fc   = (const float*)d_in[12];
    const float* b_fc   = (const float*)d_in[13];
    float* out = (float*)d_out;

    probe_kernel<<<1, 1024>>>((const unsigned int*)edges);
    convert_edges<<<(EE + 255) / 256, 256>>>(edges);
    zero_deg<<<(NN + 255) / 256, 256>>>();
    hist_kernel<<<(EE + 255) / 256, 256>>>();
    dinv_kernel<<<(NN + 255) / 256, 256>>>();

    int nodeWarps = (NN * 32 + 255) / 256;
    int edgeWarps = (EE * 32 + 255) / 256;

    // layer0: h = leaky(x @ w_hid.T + b_hid)
    k_linear<256, 128, 0><<<nodeWarps, 256>>>(x, w_hid, b_hid, g_h);

    // conv1: 3 iterations, H=128
    for (int it = 0; it < 3; it++) {
        k_msg<<<nodeWarps, 256>>>(g_h, gcn_w1, g_msg, 128);
        k_anti<128><<<nodeWarps, 256>>>(g_h, W_a1, g_anti);
        k_selfinit<<<(NN * 128 + 255) / 256, 256>>>(g_agg, g_msg, 128);
        k_scatter_v4<<<edgeWarps, 256>>>(g_msg, g_agg);
        k_update<<<(NN * 128 + 255) / 256, 256>>>(g_h, g_anti, g_agg, b_a1, 128);
    }

    // hid2: h2 = leaky(leaky(h) @ w_hid2.T + b_hid2)
    k_linear<128, 64, 1><<<nodeWarps, 256>>>(g_h, w_hid2, b_hid2, g_h2);

    // conv2: 1 iteration, H=64
    k_msg<<<nodeWarps, 256>>>(g_h2, gcn_w2, g_msg, 64);
    k_anti<64><<<nodeWarps, 256>>>(g_h2, W_a2, g_anti);
    k_selfinit<<<(NN * 64 + 255) / 256, 256>>>(g_agg, g_msg, 64);
    k_scatter_v2<<<edgeWarps, 256>>>(g_msg, g_agg);
    k_update<<<(NN * 64 + 255) / 256, 256>>>(g_h2, g_anti, g_agg, b_a2, 64);

    // fc + log_softmax
    k_fc<<<(NN + 255) / 256, 256>>>(g_h2, w_fc, b_fc, out);
}

// round 8
// speedup vs baseline: 3.1760x; 1.5582x over previous
#include <cuda_runtime.h>
#include <math.h>

#define LEAKY_SLOPE 0.01f
#define EPS_C 0.1f
#define GAMMA_C 0.1f

#define NN 50000
#define EE 600000

// ---------------- scratch (node/edge data only; no weight copies!) ----------------
__device__ __align__(16) float g_h   [NN * 128];
__device__ __align__(16) float g_h2  [NN * 64];
__device__ __align__(16) float g_msg [NN * 128];
__device__ __align__(16) float g_anti[NN * 128];
__device__ int   g_deg   [NN];
__device__ float g_dinv  [NN];
__device__ int   g_src   [EE];
__device__ int   g_dst   [EE];
__device__ int   g_rowptr[NN + 1];
__device__ int   g_cursor[NN];
__device__ int   g_colidx[EE];
__device__ int   g_is64;

__device__ __forceinline__ float lky(float x) { return x > 0.f ? x : LEAKY_SLOPE * x; }
__device__ __forceinline__ int clampN(int v) { return v < 0 ? 0 : (v >= NN ? NN - 1 : v); }

// ---------------- edge dtype probe + convert (layout [2, E] row-major) ----------------
__global__ void probe_kernel(const unsigned int* __restrict__ w) {
    __shared__ int fl;
    if (threadIdx.x == 0) fl = 0;
    __syncthreads();
    for (int i = 1 + 2 * (int)threadIdx.x; i < 16384; i += 2 * (int)blockDim.x)
        if (w[i] != 0u) fl = 1;
    __syncthreads();
    if (threadIdx.x == 0) g_is64 = (fl == 0) ? 1 : 0;
}

__global__ void convert_edges(const void* __restrict__ raw) {
    int i = blockIdx.x * blockDim.x + threadIdx.x;
    if (i >= EE) return;
    int s, d;
    if (g_is64) {
        const long long* p = (const long long*)raw;
        s = (int)p[i];
        d = (int)p[EE + i];
    } else {
        const int* p = (const int*)raw;
        s = p[i];
        d = p[EE + i];
    }
    g_src[i] = clampN(s);
    g_dst[i] = clampN(d);
}

// ---------------- degree / norm ----------------
__global__ void zero_deg() {
    int i = blockIdx.x * blockDim.x + threadIdx.x;
    if (i < NN) g_deg[i] = 0;
}
__global__ void hist_kernel() {
    int i = blockIdx.x * blockDim.x + threadIdx.x;
    if (i < EE) atomicAdd(&g_deg[g_dst[i]], 1);
}
__global__ void dinv_kernel() {
    int i = blockIdx.x * blockDim.x + threadIdx.x;
    if (i < NN) g_dinv[i] = rsqrtf((float)(g_deg[i] + 1));  // +1 self loop
}

// ---------------- CSR build (by dst) ----------------
__global__ void scan_kernel() {
    __shared__ int sh[1024];
    __shared__ int carry;
    int t = threadIdx.x;
    if (t == 0) carry = 0;
    __syncthreads();
    for (int base = 0; base < NN; base += 1024) {
        int v = (base + t < NN) ? g_deg[base + t] : 0;
        sh[t] = v;
        __syncthreads();
        for (int off = 1; off < 1024; off <<= 1) {
            int add = (t >= off) ? sh[t - off] : 0;
            __syncthreads();
            sh[t] += add;
            __syncthreads();
        }
        int incl = sh[t];
        int excl = carry + incl - v;
        if (base + t < NN) g_rowptr[base + t] = excl;
        __syncthreads();
        if (t == 1023) carry += incl;
        __syncthreads();
    }
    if (t == 0) g_rowptr[NN] = carry;
}
__global__ void cursor_copy() {
    int i = blockIdx.x * blockDim.x + threadIdx.x;
    if (i < NN) g_cursor[i] = g_rowptr[i];
}
__global__ void fill_kernel() {
    int i = blockIdx.x * blockDim.x + threadIdx.x;
    if (i >= EE) return;
    int d = g_dst[i];
    int p = atomicAdd(&g_cursor[d], 1);
    if (p < EE) g_colidx[p] = g_src[i];
}

// ---------------- linear (verbatim R7) ----------------
template<int K, int J, int PREL>
__global__ void __launch_bounds__(256) k_linear(const float* __restrict__ A,
                                                const float* __restrict__ Wt,
                                                const float* __restrict__ b,
                                                float* __restrict__ C) {
    int node = (blockIdx.x * blockDim.x + threadIdx.x) >> 5;
    if (node >= NN) return;
    int lane = threadIdx.x & 31;
    const float* ar = A + (size_t)node * K;
    float xr[K / 32];
#pragma unroll
    for (int m = 0; m < K / 32; m++) {
        float v = ar[32 * m + lane];
        xr[m] = PREL ? lky(v) : v;
    }
    float outv[J / 32];
#pragma unroll
    for (int c = 0; c < J / 32; c++) outv[c] = 0.f;
    for (int j = 0; j < J; j++) {
        const float* wr = Wt + (size_t)j * K;
        float p = 0.f;
#pragma unroll
        for (int m = 0; m < K / 32; m++)
            p = fmaf(xr[m], wr[32 * m + lane], p);
#pragma unroll
        for (int o = 16; o; o >>= 1) p += __shfl_xor_sync(0xffffffffu, p, o);
        if ((j & 31) == lane) outv[j >> 5] = p;
    }
#pragma unroll
    for (int c = 0; c < J / 32; c++) {
        int j = c * 32 + lane;
        C[(size_t)node * J + j] = lky(outv[c] + b[j]);
    }
}

// ---------------- msg (verbatim R7) ----------------
__global__ void k_msg(const float* __restrict__ h, const float* __restrict__ Wg,
                      float* __restrict__ msg, int H) {
    int node = (blockIdx.x * blockDim.x + threadIdx.x) >> 5;
    if (node >= NN) return;
    int lane = threadIdx.x & 31;
    const float* hr = h + (size_t)node * H;
    for (int c = 0; c < H; c += 32) {
        int j = c + lane;
        float acc = 0.f;
        for (int k = 0; k < H; k++)
            acc += hr[k] * Wg[(size_t)k * H + j];
        msg[(size_t)node * H + j] = acc;
    }
}

// ---------------- anti (verbatim R7) ----------------
template<int H>
__global__ void __launch_bounds__(256) k_anti(const float* __restrict__ h,
                                              const float* __restrict__ W,
                                              float* __restrict__ anti) {
    __shared__ float t1[8][H];
    __shared__ float hs[8][H];
    int warp = threadIdx.x >> 5;
    int node = (blockIdx.x * blockDim.x + threadIdx.x) >> 5;
    if (node >= NN) return;
    int lane = threadIdx.x & 31;
    const float* hr = h + (size_t)node * H;
    float xr[H / 32];
#pragma unroll
    for (int m = 0; m < H / 32; m++) {
        xr[m] = hr[32 * m + lane];
        hs[warp][32 * m + lane] = xr[m];
    }
    __syncwarp();
    for (int j = 0; j < H; j++) {
        const float* wr = W + (size_t)j * H;
        float p = 0.f;
#pragma unroll
        for (int m = 0; m < H / 32; m++)
            p = fmaf(xr[m], wr[32 * m + lane], p);
#pragma unroll
        for (int o = 16; o; o >>= 1) p += __shfl_xor_sync(0xffffffffu, p, o);
        if (lane == 0) t1[warp][j] = p;
    }
    __syncwarp();
#pragma unroll
    for (int c = 0; c < H / 32; c++) {
        int j = c * 32 + lane;
        float acc = 0.f;
        for (int k = 0; k < H; k++)
            acc = fmaf(hs[warp][k], W[(size_t)k * H + j], acc);
        anti[(size_t)node * H + j] = t1[warp][j] - acc - GAMMA_C * xr[c];
    }
}

// ---------------- fused gather + update: h += eps*tanh(anti + agg + bias) ----------------
// agg_j = msg[i][j]*di*di + sum_{s in N(i)} msg[s][j]*dinv[s]*di
template<int H>
__global__ void __launch_bounds__(256) k_gather_update(float* __restrict__ h,
                                                       const float* __restrict__ msg,
                                                       const float* __restrict__ anti,
                                                       const float* __restrict__ bias) {
    int node = (blockIdx.x * blockDim.x + threadIdx.x) >> 5;
    if (node >= NN) return;
    int lane = threadIdx.x & 31;
    constexpr int C = H / 32;
    float di = g_dinv[node];
    const float* mr = msg + (size_t)node * H;
    float acc[C];
#pragma unroll
    for (int c = 0; c < C; c++)
        acc[c] = mr[c * 32 + lane] * di * di;   // self loop
    int e0 = g_rowptr[node], e1 = g_rowptr[node + 1];
    for (int e = e0; e < e1; e++) {
        int s = g_colidx[e];
        float w = g_dinv[s] * di;
        const float* ms = msg + (size_t)s * H;
#pragma unroll
        for (int c = 0; c < C; c++)
            acc[c] = fmaf(ms[c * 32 + lane], w, acc[c]);
    }
#pragma unroll
    for (int c = 0; c < C; c++) {
        int j = c * 32 + lane;
        size_t idx = (size_t)node * H + j;
        h[idx] += EPS_C * tanhf(anti[idx] + acc[c] + bias[j]);
    }
}

// ---------------- fc + log_softmax, thread per node (verbatim R7) ----------------
__global__ void k_fc(const float* __restrict__ h2, const float* __restrict__ wfc,
                     const float* __restrict__ bfc, float* __restrict__ out) {
    int i = blockIdx.x * blockDim.x + threadIdx.x;
    if (i >= NN) return;
    float hv[64];
    const float* hr = h2 + (size_t)i * 64;
    for (int k = 0; k < 64; k++) hv[k] = hr[k];
    float lg[40];
    float m = -1e30f;
    for (int j = 0; j < 40; j++) {
        float acc = bfc[j];
        for (int k = 0; k < 64; k++)
            acc += hv[k] * wfc[(size_t)j * 64 + k];
        lg[j] = acc;
        m = fmaxf(m, acc);
    }
    float s = 0.f;
    for (int j = 0; j < 40; j++) s += expf(lg[j] - m);
    float lse = m + logf(s);
    float* o = out + (size_t)i * 40;
    for (int j = 0; j < 40; j++) o[j] = lg[j] - lse;
}

// ---------------- launch ----------------
extern "C" void kernel_launch(void* const* d_in, const int* in_sizes, int n_in,
                              void* d_out, int out_size) {
    const float* x      = (const float*)d_in[0];
    const void*  edges  = d_in[1];
    const float* w_hid  = (const float*)d_in[2];
    const float* b_hid  = (const float*)d_in[3];
    const float* W_a1   = (const float*)d_in[4];
    const float* gcn_w1 = (const float*)d_in[5];
    const float* b_a1   = (const float*)d_in[6];
    const float* w_hid2 = (const float*)d_in[7];
    const float* b_hid2 = (const float*)d_in[8];
    const float* W_a2   = (const float*)d_in[9];
    const float* gcn_w2 = (const float*)d_in[10];
    const float* b_a2   = (const float*)d_in[11];
    const float* w_fc   = (const float*)d_in[12];
    const float* b_fc   = (const float*)d_in[13];
    float* out = (float*)d_out;

    probe_kernel<<<1, 1024>>>((const unsigned int*)edges);
    convert_edges<<<(EE + 255) / 256, 256>>>(edges);
    zero_deg<<<(NN + 255) / 256, 256>>>();
    hist_kernel<<<(EE + 255) / 256, 256>>>();
    dinv_kernel<<<(NN + 255) / 256, 256>>>();

    // CSR by dst
    scan_kernel<<<1, 1024>>>();
    cursor_copy<<<(NN + 255) / 256, 256>>>();
    fill_kernel<<<(EE + 255) / 256, 256>>>();

    int nodeWarps = (NN * 32 + 255) / 256;

    // layer0: h = leaky(x @ w_hid.T + b_hid)
    k_linear<256, 128, 0><<<nodeWarps, 256>>>(x, w_hid, b_hid, g_h);

    // conv1: 3 iterations, H=128
    for (int it = 0; it < 3; it++) {
        k_msg<<<nodeWarps, 256>>>(g_h, gcn_w1, g_msg, 128);
        k_anti<128><<<nodeWarps, 256>>>(g_h, W_a1, g_anti);
        k_gather_update<128><<<nodeWarps, 256>>>(g_h, g_msg, g_anti, b_a1);
    }

    // hid2: h2 = leaky(leaky(h) @ w_hid2.T + b_hid2)
    k_linear<128, 64, 1><<<nodeWarps, 256>>>(g_h, w_hid2, b_hid2, g_h2);

    // conv2: 1 iteration, H=64
    k_msg<<<nodeWarps, 256>>>(g_h2, gcn_w2, g_msg, 64);
    k_anti<64><<<nodeWarps, 256>>>(g_h2, W_a2, g_anti);
    k_gather_update<64><<<nodeWarps, 256>>>(g_h2, g_msg, g_anti, b_a2);

    // fc + log_softmax
    k_fc<<<(NN + 255) / 256, 256>>>(g_h2, w_fc, b_fc, out);
}

// round 9
// speedup vs baseline: 3.3016x; 1.0395x over previous
#include <cuda_runtime.h>
#include <math.h>

#define LEAKY_SLOPE 0.01f
#define EPS_C 0.1f
#define GAMMA_C 0.1f

#define NN 50000
#define EE 600000

// ---------------- scratch (node/edge data only; NO weight-copy arrays) ----------------
__device__ __align__(16) float g_h   [NN * 128];
__device__ __align__(16) float g_h2  [NN * 64];
__device__ __align__(16) float g_buf [NN * 256];   // fused [msg | anti] rows
__device__ int   g_deg   [NN];
__device__ float g_dinv  [NN];
__device__ int   g_src   [EE];
__device__ int   g_dst   [EE];
__device__ int   g_rowptr[NN + 1];
__device__ int   g_cursor[NN];
__device__ int   g_colidx[EE];
__device__ int   g_is64;

__device__ __forceinline__ float lky(float x) { return x > 0.f ? x : LEAKY_SLOPE * x; }
__device__ __forceinline__ int clampN(int v) { return v < 0 ? 0 : (v >= NN ? NN - 1 : v); }

// ---------------- edge dtype probe + convert (layout [2, E] row-major) ----------------
__global__ void probe_kernel(const unsigned int* __restrict__ w) {
    __shared__ int fl;
    if (threadIdx.x == 0) fl = 0;
    __syncthreads();
    for (int i = 1 + 2 * (int)threadIdx.x; i < 16384; i += 2 * (int)blockDim.x)
        if (w[i] != 0u) fl = 1;
    __syncthreads();
    if (threadIdx.x == 0) g_is64 = (fl == 0) ? 1 : 0;
}

__global__ void convert_edges(const void* __restrict__ raw) {
    int i = blockIdx.x * blockDim.x + threadIdx.x;
    if (i >= EE) return;
    int s, d;
    if (g_is64) {
        const long long* p = (const long long*)raw;
        s = (int)p[i];
        d = (int)p[EE + i];
    } else {
        const int* p = (const int*)raw;
        s = p[i];
        d = p[EE + i];
    }
    g_src[i] = clampN(s);
    g_dst[i] = clampN(d);
}

// ---------------- degree / norm ----------------
__global__ void zero_deg() {
    int i = blockIdx.x * blockDim.x + threadIdx.x;
    if (i < NN) g_deg[i] = 0;
}
__global__ void hist_kernel() {
    int i = blockIdx.x * blockDim.x + threadIdx.x;
    if (i < EE) atomicAdd(&g_deg[g_dst[i]], 1);
}
__global__ void dinv_kernel() {
    int i = blockIdx.x * blockDim.x + threadIdx.x;
    if (i < NN) g_dinv[i] = rsqrtf((float)(g_deg[i] + 1));  // +1 self loop
}

// ---------------- CSR build (by dst), verbatim R8 ----------------
__global__ void scan_kernel() {
    __shared__ int sh[1024];
    __shared__ int carry;
    int t = threadIdx.x;
    if (t == 0) carry = 0;
    __syncthreads();
    for (int base = 0; base < NN; base += 1024) {
        int v = (base + t < NN) ? g_deg[base + t] : 0;
        sh[t] = v;
        __syncthreads();
        for (int off = 1; off < 1024; off <<= 1) {
            int add = (t >= off) ? sh[t - off] : 0;
            __syncthreads();
            sh[t] += add;
            __syncthreads();
        }
        int incl = sh[t];
        int excl = carry + incl - v;
        if (base + t < NN) g_rowptr[base + t] = excl;
        __syncthreads();
        if (t == 1023) carry += incl;
        __syncthreads();
    }
    if (t == 0) g_rowptr[NN] = carry;
}
__global__ void cursor_copy() {
    int i = blockIdx.x * blockDim.x + threadIdx.x;
    if (i < NN) g_cursor[i] = g_rowptr[i];
}
__global__ void fill_kernel() {
    int i = blockIdx.x * blockDim.x + threadIdx.x;
    if (i >= EE) return;
    int d = g_dst[i];
    int p = atomicAdd(&g_cursor[d], 1);
    if (p < EE) g_colidx[p] = g_src[i];
}

// ---------------- tiled GEMM, B built on the fly from RAW weights ----------------
// C[i][j] = postAct( preAct(A[i]) @ B + bias ),  BM=128, BN=64, BK=16, 256 thr, 8x4/thread.
// BMODE 0: B[k][j] = W1[j*K + k]                      (transposed linear weight, [J][K] raw)
// BMODE 1: j < J/2 : B[k][j] = W1[k*(J/2) + j]         (gcn_w, [H][H] raw)
//          j >= J/2: B[k][j] = W2[jj*(J/2)+k] - W2[k*(J/2)+jj] - (k==jj)*gamma   (aW.T)
template<int K, int J, int BMODE, int PREL, int POSTL>
__global__ void __launch_bounds__(256)
gemm_kernel(const float* __restrict__ A, const float* __restrict__ W1,
            const float* __restrict__ W2, const float* __restrict__ bias,
            float* __restrict__ C) {
    __shared__ float sA[16][128 + 4];
    __shared__ float sB[16][64];
    int tid = threadIdx.x;
    int tx = tid & 15;   // col group (4 cols)
    int ty = tid >> 4;   // row group (8 rows)
    int row0 = blockIdx.x * 128;
    int col0 = blockIdx.y * 64;
    constexpr int HALF = J / 2;

    float acc[8][4];
#pragma unroll
    for (int r = 0; r < 8; r++)
#pragma unroll
        for (int c = 0; c < 4; c++) acc[r][c] = 0.f;

    for (int kt = 0; kt < K; kt += 16) {
        // A tile: 128 rows x 16 k, transposed into sA[k][row]
#pragma unroll
        for (int li = 0; li < 2; li++) {
            int idx = tid + li * 256;
            int r = idx >> 2;
            int k4 = (idx & 3) * 4;
            float4 v = make_float4(0.f, 0.f, 0.f, 0.f);
            int gr = row0 + r;
            if (gr < NN) v = *(const float4*)(A + (size_t)gr * K + kt + k4);
            if (PREL) { v.x = lky(v.x); v.y = lky(v.y); v.z = lky(v.z); v.w = lky(v.w); }
            sA[k4 + 0][r] = v.x;
            sA[k4 + 1][r] = v.y;
            sA[k4 + 2][r] = v.z;
            sA[k4 + 3][r] = v.w;
        }
        // B tile: 16 k x 64 j, computed from raw weights
        {
            int k = tid >> 4;          // 0..15
            int j4 = (tid & 15) * 4;   // 0..60
            int kk = kt + k;
#pragma unroll
            for (int i = 0; i < 4; i++) {
                int j = col0 + j4 + i;
                float v;
                if (BMODE == 0) {
                    v = W1[(size_t)j * K + kk];
                } else {
                    if (j < HALF) {
                        v = W1[(size_t)kk * HALF + j];
                    } else {
                        int jj = j - HALF;
                        v = W2[(size_t)jj * HALF + kk] - W2[(size_t)kk * HALF + jj]
                            - ((kk == jj) ? GAMMA_C : 0.f);
                    }
                }
                sB[k][j4 + i] = v;
            }
        }
        __syncthreads();
#pragma unroll
        for (int k = 0; k < 16; k++) {
            float4 b = *(const float4*)&sB[k][tx * 4];
            float4 a0 = *(const float4*)&sA[k][ty * 8];
            float4 a1 = *(const float4*)&sA[k][ty * 8 + 4];
            float ar[8] = {a0.x, a0.y, a0.z, a0.w, a1.x, a1.y, a1.z, a1.w};
#pragma unroll
            for (int r = 0; r < 8; r++) {
                acc[r][0] = fmaf(ar[r], b.x, acc[r][0]);
                acc[r][1] = fmaf(ar[r], b.y, acc[r][1]);
                acc[r][2] = fmaf(ar[r], b.z, acc[r][2]);
                acc[r][3] = fmaf(ar[r], b.w, acc[r][3]);
            }
        }
        __syncthreads();
    }

    float4 bv = make_float4(0.f, 0.f, 0.f, 0.f);
    if (bias) bv = *(const float4*)(bias + col0 + tx * 4);
#pragma unroll
    for (int r = 0; r < 8; r++) {
        int gr = row0 + ty * 8 + r;
        if (gr < NN) {
            float4 o = make_float4(acc[r][0] + bv.x, acc[r][1] + bv.y,
                                   acc[r][2] + bv.z, acc[r][3] + bv.w);
            if (POSTL) { o.x = lky(o.x); o.y = lky(o.y); o.z = lky(o.z); o.w = lky(o.w); }
            *(float4*)(C + (size_t)gr * J + col0 + tx * 4) = o;
        }
    }
}

// ---------------- fused gather + update (R8 pattern; buf row = [msg | anti], stride RS) ------
template<int H, int RS>
__global__ void __launch_bounds__(256) k_gather_update(float* __restrict__ h,
                                                       const float* __restrict__ buf,
                                                       const float* __restrict__ bias) {
    int node = (blockIdx.x * blockDim.x + threadIdx.x) >> 5;
    if (node >= NN) return;
    int lane = threadIdx.x & 31;
    constexpr int C = H / 32;
    float di = g_dinv[node];
    const float* mr = buf + (size_t)node * RS;
    float acc[C];
#pragma unroll
    for (int c = 0; c < C; c++)
        acc[c] = mr[c * 32 + lane] * di * di;   // self loop
    int e0 = g_rowptr[node], e1 = g_rowptr[node + 1];
    for (int e = e0; e < e1; e++) {
        int s = g_colidx[e];
        float w = g_dinv[s] * di;
        const float* ms = buf + (size_t)s * RS;
#pragma unroll
        for (int c = 0; c < C; c++)
            acc[c] = fmaf(ms[c * 32 + lane], w, acc[c]);
    }
#pragma unroll
    for (int c = 0; c < C; c++) {
        int j = c * 32 + lane;
        float anti = mr[H + j];                 // anti half (includes -gamma*h)
        size_t idx = (size_t)node * H + j;
        h[idx] += EPS_C * tanhf(anti + acc[c] + bias[j]);
    }
}

// ---------------- fc + log_softmax, thread per node (verbatim R8) ----------------
__global__ void k_fc(const float* __restrict__ h2, const float* __restrict__ wfc,
                     const float* __restrict__ bfc, float* __restrict__ out) {
    int i = blockIdx.x * blockDim.x + threadIdx.x;
    if (i >= NN) return;
    float hv[64];
    const float* hr = h2 + (size_t)i * 64;
    for (int k = 0; k < 64; k++) hv[k] = hr[k];
    float lg[40];
    float m = -1e30f;
    for (int j = 0; j < 40; j++) {
        float acc = bfc[j];
        for (int k = 0; k < 64; k++)
            acc += hv[k] * wfc[(size_t)j * 64 + k];
        lg[j] = acc;
        m = fmaxf(m, acc);
    }
    float s = 0.f;
    for (int j = 0; j < 40; j++) s += expf(lg[j] - m);
    float lse = m + logf(s);
    float* o = out + (size_t)i * 40;
    for (int j = 0; j < 40; j++) o[j] = lg[j] - lse;
}

// ---------------- launch ----------------
extern "C" void kernel_launch(void* const* d_in, const int* in_sizes, int n_in,
                              void* d_out, int out_size) {
    const float* x      = (const float*)d_in[0];
    const void*  edges  = d_in[1];
    const float* w_hid  = (const float*)d_in[2];
    const float* b_hid  = (const float*)d_in[3];
    const float* W_a1   = (const float*)d_in[4];
    const float* gcn_w1 = (const float*)d_in[5];
    const float* b_a1   = (const float*)d_in[6];
    const float* w_hid2 = (const float*)d_in[7];
    const float* b_hid2 = (const float*)d_in[8];
    const float* W_a2   = (const float*)d_in[9];
    const float* gcn_w2 = (const float*)d_in[10];
    const float* b_a2   = (const float*)d_in[11];
    const float* w_fc   = (const float*)d_in[12];
    const float* b_fc   = (const float*)d_in[13];
    float* out = (float*)d_out;

    probe_kernel<<<1, 1024>>>((const unsigned int*)edges);
    convert_edges<<<(EE + 255) / 256, 256>>>(edges);
    zero_deg<<<(NN + 255) / 256, 256>>>();
    hist_kernel<<<(EE + 255) / 256, 256>>>();
    dinv_kernel<<<(NN + 255) / 256, 256>>>();

    scan_kernel<<<1, 1024>>>();
    cursor_copy<<<(NN + 255) / 256, 256>>>();
    fill_kernel<<<(EE + 255) / 256, 256>>>();

    int gx = (NN + 127) / 128;
    int nodeWarps = (NN * 32 + 255) / 256;

    // layer0: h = leaky(x @ w_hid.T + b_hid)   [N,256]->[N,128]
    gemm_kernel<256, 128, 0, 0, 1><<<dim3(gx, 2), 256>>>(x, w_hid, nullptr, b_hid, g_h);

    // conv1: 3 iterations, H=128: fused [msg|anti] GEMM -> gather+update
    for (int it = 0; it < 3; it++) {
        gemm_kernel<128, 256, 1, 0, 0><<<dim3(gx, 4), 256>>>(g_h, gcn_w1, W_a1, nullptr, g_buf);
        k_gather_update<128, 256><<<nodeWarps, 256>>>(g_h, g_buf, b_a1);
    }

    // hid2: h2 = leaky(leaky(h) @ w_hid2.T + b_hid2)   [N,128]->[N,64]
    gemm_kernel<128, 64, 0, 1, 1><<<dim3(gx, 1), 256>>>(g_h, w_hid2, nullptr, b_hid2, g_h2);

    // conv2: 1 iteration, H=64
    gemm_kernel<64, 128, 1, 0, 0><<<dim3(gx, 2), 256>>>(g_h2, gcn_w2, W_a2, nullptr, g_buf);
    k_gather_update<64, 128><<<nodeWarps, 256>>>(g_h2, g_buf, b_a2);

    // fc + log_softmax
    k_fc<<<(NN + 255) / 256, 256>>>(g_h2, w_fc, b_fc, out);
}